// round 12
// baseline (speedup 1.0000x reference)
#include <cuda_runtime.h>
#include <cuda_fp16.h>
#include <stdint.h>

// Problem constants (match reference_code)
#define N_USERS 200000
#define N_ITEMS 100000
#define N_BOTH  (N_USERS + N_ITEMS)
#define NNZ_CAP 5000000
#define D       128           // feature dim
#define SCAN_B  1024

// ---------------- scratch (device globals; no runtime allocation) ----------
__device__ __half   g_yh[(size_t)N_USERS * D];    // fp16 intermediate, 51.2 MB
__device__ unsigned g_xq[(size_t)N_ITEMS * (D/4)];// int8 x, packed 4/word, 12.8 MB
__device__ float    g_xscale[N_ITEMS];            // per-item-row scale (max/127)
__device__ float2   g_degcnt[N_BOTH];             // (deg, count) per node
__device__ float    g_dinv[N_BOTH];               // clamp(deg,1)^-0.5
__device__ int      g_off[N_BOTH];                // unified exclusive-scan offsets
__device__ int      g_cur[N_BOTH];                // working cursors for scatter
__device__ int      g_bsums[SCAN_B];              // scan block sums scratch
__device__ unsigned g_epack[(size_t)2 * NNZ_CAP]; // packed [CSR | CSC], 40 MB
// CSR word: (halfbits(nv * xscale[col]) << 17) | col   (col < 2^17, sign 0)
// CSC word: (((halfbits(nv)+1)>>1) << 18) | row        (row < 2^18, 14-bit nv)

// ---------------- helpers ----------------------------------------------------

__device__ __forceinline__ void red_add_v2(float2* addr, float a, float b) {
    asm volatile("red.global.add.v2.f32 [%0], {%1, %2};"
                 :: "l"(addr), "f"(a), "f"(b) : "memory");
}

// ---------------- kernels ---------------------------------------------------

__global__ void zero_i4_kernel(int4* __restrict__ p, int n4) {
    int i = blockIdx.x * blockDim.x + threadIdx.x;
    if (i < n4) p[i] = make_int4(0, 0, 0, 0);
}

// fused front: [0, ablocks) = degree+count histogram;
// [ablocks, ...) = per-row int8 quantization of x (warp per item row).
__global__ void front_kernel(const float* __restrict__ vals,
                             const int* __restrict__ rows,
                             const int* __restrict__ cols,
                             const float4* __restrict__ x,
                             int nnz, int ablocks) {
    if (blockIdx.x < (unsigned)ablocks) {
        int e = blockIdx.x * blockDim.x + threadIdx.x;
        if (e >= nnz) return;
        float v = __ldcs(vals + e);
        red_add_v2(&g_degcnt[__ldcs(rows + e)], v, 1.0f);
        red_add_v2(&g_degcnt[__ldcs(cols + e) + N_USERS], v, 1.0f);
        return;
    }
    // quantize: one warp per item row (128 floats -> 128 int8 + 1 scale)
    int gt   = (blockIdx.x - ablocks) * blockDim.x + threadIdx.x;
    int row  = gt >> 5;
    int lane = gt & 31;
    if (row >= N_ITEMS) return;

    float4 v = __ldg(x + (size_t)row * (D / 4) + lane);
    float m = fmaxf(fmaxf(fabsf(v.x), fabsf(v.y)), fmaxf(fabsf(v.z), fabsf(v.w)));
    #pragma unroll
    for (int o = 16; o > 0; o >>= 1)
        m = fmaxf(m, __shfl_xor_sync(0xffffffffu, m, o));

    float inv = (m > 0.f) ? 127.f / m : 0.f;
    int q0 = __float2int_rn(v.x * inv);
    int q1 = __float2int_rn(v.y * inv);
    int q2 = __float2int_rn(v.z * inv);
    int q3 = __float2int_rn(v.w * inv);
    unsigned packed = (unsigned)(q0 & 0xff) | ((unsigned)(q1 & 0xff) << 8) |
                      ((unsigned)(q2 & 0xff) << 16) | ((unsigned)(q3 & 0xff) << 24);
    g_xq[(size_t)row * (D / 4) + lane] = packed;
    if (lane == 0) g_xscale[row] = (m > 0.f) ? m / 127.f : 0.f;
}

// ---- unified exclusive scan over all N_BOTH counts, with fused prep -------
__global__ void scan_block_kernel(int* __restrict__ out, int* __restrict__ bsums,
                                  int n) {
    __shared__ int sh[SCAN_B];
    int i = blockIdx.x * SCAN_B + threadIdx.x;
    int v = 0;
    if (i < n) {
        float2 dc = g_degcnt[i];
        v = (int)dc.y;
        g_dinv[i] = rsqrtf(fmaxf(dc.x, 1.0f));
    }
    sh[threadIdx.x] = v;
    __syncthreads();
    #pragma unroll
    for (int off = 1; off < SCAN_B; off <<= 1) {
        int t = (threadIdx.x >= (unsigned)off) ? sh[threadIdx.x - off] : 0;
        __syncthreads();
        sh[threadIdx.x] += t;
        __syncthreads();
    }
    if (i < n) out[i] = sh[threadIdx.x] - v;          // exclusive
    if (threadIdx.x == SCAN_B - 1) bsums[blockIdx.x] = sh[SCAN_B - 1];
}

__global__ void scan_sums_kernel(int* __restrict__ bsums, int nb) {
    __shared__ int sh[SCAN_B];
    int v = (threadIdx.x < (unsigned)nb) ? bsums[threadIdx.x] : 0;
    sh[threadIdx.x] = v;
    __syncthreads();
    #pragma unroll
    for (int off = 1; off < SCAN_B; off <<= 1) {
        int t = (threadIdx.x >= (unsigned)off) ? sh[threadIdx.x - off] : 0;
        __syncthreads();
        sh[threadIdx.x] += t;
        __syncthreads();
    }
    if (threadIdx.x < (unsigned)nb) bsums[threadIdx.x] = sh[threadIdx.x] - v;  // exclusive
}

__global__ void scan_add_kernel(int* __restrict__ off_, int* __restrict__ cur,
                                const int* __restrict__ bsums, int n) {
    int i = blockIdx.x * SCAN_B + threadIdx.x;
    if (i < n) {
        int o = off_[i] + bsums[blockIdx.x];
        off_[i] = o;
        cur[i] = o;
    }
}

// scatter packed edges into unified [CSR | CSC]; CSR weight folds x row scale
__global__ void build_kernel(const float* __restrict__ vals,
                             const int* __restrict__ rows,
                             const int* __restrict__ cols,
                             int nnz) {
    int e = blockIdx.x * blockDim.x + threadIdx.x;
    if (e >= nnz) return;
    int r = __ldcs(rows + e);
    int c = __ldcs(cols + e);
    float nv = __ldcs(vals + e) * g_dinv[r] * g_dinv[c + N_USERS];
    float nvx = nv * __ldg(&g_xscale[c]);            // folded int8 scale
    unsigned hbu = (unsigned)__half_as_ushort(__float2half_rn(nvx));
    unsigned hbi = (unsigned)__half_as_ushort(__float2half_rn(nv));
    unsigned wu = (hbu << 17) | (unsigned)c;
    unsigned wi = (((hbi + 1u) >> 1) << 18) | (unsigned)r;
    int pu = atomicAdd(&g_cur[r], 1);
    __stcs(g_epack + pu, wu);
    int pi = atomicAdd(&g_cur[c + N_USERS], 1);
    __stcs(g_epack + pi, wi);
}

// ---- pass 1: int8 gather (8 bytes per lane), scale pre-folded into vv ------
// NOTE: explicit sign extension — plain `char` is UNSIGNED on aarch64.
__device__ __forceinline__ float sx8(unsigned w, int byte) {
    return (float)((int)(w << ((3 - byte) * 8)) >> 24);
}

__device__ __forceinline__ void acc_step_i8(int idx, float vv, int sub,
                                            float* acc) {
    uint2 u = __ldg(reinterpret_cast<const uint2*>(g_xq + (size_t)idx * (D / 4)) + sub);
    acc[0] += vv * sx8(u.x, 0);
    acc[1] += vv * sx8(u.x, 1);
    acc[2] += vv * sx8(u.x, 2);
    acc[3] += vv * sx8(u.x, 3);
    acc[4] += vv * sx8(u.y, 0);
    acc[5] += vv * sx8(u.y, 1);
    acc[6] += vv * sx8(u.y, 2);
    acc[7] += vv * sx8(u.y, 3);
}

// ---- pass 2: fp16 gather (16 bytes per lane) ------------------------------
__device__ __forceinline__ void acc_step_h(int idx, float vv, int sub,
                                           float* acc) {
    uint4 u = __ldg(reinterpret_cast<const uint4*>(g_yh + (size_t)idx * D) + sub);
    __half2 h0 = *(__half2*)&u.x, h1 = *(__half2*)&u.y;
    __half2 h2 = *(__half2*)&u.z, h3 = *(__half2*)&u.w;
    float2 f0 = __half22float2(h0), f1 = __half22float2(h1);
    float2 f2 = __half22float2(h2), f3 = __half22float2(h3);
    acc[0] += vv * f0.x; acc[1] += vv * f0.y;
    acc[2] += vv * f1.x; acc[3] += vv * f1.y;
    acc[4] += vv * f2.x; acc[5] += vv * f2.y;
    acc[6] += vv * f3.x; acc[7] += vv * f3.y;
}

// pass 1: y[u, :] = sum_{e in row u} nv_e * xscale_c * xq[col_e, :]
__global__ void spmm1_kernel(int nrows) {
    int w    = (blockIdx.x * blockDim.x + threadIdx.x) >> 5;
    int lane = threadIdx.x & 31;
    if (w >= nrows) return;
    int half = lane >> 4;
    int sub  = lane & 15;

    int s   = __ldg(&g_off[w]);
    int cnt = (int)__ldg(&g_degcnt[w].y);
    int end = s + cnt;

    float acc[8];
    #pragma unroll
    for (int i = 0; i < 8; i++) acc[i] = 0.f;

    // software-pipelined packed-record loop; CSR decode: 17 idx bits
    int j0 = s + lane;
    unsigned er = (j0 < end) ? __ldcs(g_epack + j0) : 0u;
    for (int base = s; base < end; base += 32) {
        int m = min(32, end - base);
        unsigned cur_er = er;
        if (base + 32 < end) {
            int jn = base + 32 + lane;
            er = (jn < end) ? __ldcs(g_epack + jn) : 0u;
        }
        int pairs = (m + 1) >> 1;
        for (int p = 0; p < pairs; p++) {
            int eidx = (p << 1) + half;
            unsigned wd = __shfl_sync(0xffffffffu, cur_er, eidx);
            if (eidx < m) {
                int idx = (int)(wd & 0x1ffffu);
                float vv = __half2float(__ushort_as_half((unsigned short)(wd >> 17)));
                acc_step_i8(idx, vv, sub, acc);
            }
        }
    }

    #pragma unroll
    for (int i = 0; i < 8; i++) acc[i] += __shfl_xor_sync(0xffffffffu, acc[i], 16);

    if (half == 0) {
        __half2 o0 = __floats2half2_rn(acc[0], acc[1]);
        __half2 o1 = __floats2half2_rn(acc[2], acc[3]);
        __half2 o2 = __floats2half2_rn(acc[4], acc[5]);
        __half2 o3 = __floats2half2_rn(acc[6], acc[7]);
        reinterpret_cast<uint4*>(g_yh + (size_t)w * D)[sub] =
            make_uint4(*(unsigned*)&o0, *(unsigned*)&o1,
                       *(unsigned*)&o2, *(unsigned*)&o3);
    }
}

// pass 2 + finalize: out[i, :] = x[i, :] - 2 * sum_{e in col i} nv_e * y_h[row_e, :]
__global__ void spmm2_kernel(const float* __restrict__ x,
                             float* __restrict__ out, int nrows) {
    int w    = (blockIdx.x * blockDim.x + threadIdx.x) >> 5;
    int lane = threadIdx.x & 31;
    if (w >= nrows) return;
    int half = lane >> 4;
    int sub  = lane & 15;

    int s   = __ldg(&g_off[w + N_USERS]);
    int cnt = (int)__ldg(&g_degcnt[w + N_USERS].y);
    int end = s + cnt;

    float acc[8];
    #pragma unroll
    for (int i = 0; i < 8; i++) acc[i] = 0.f;

    // software-pipelined packed-record loop; CSC decode: 18 idx bits, 14-bit nv
    int j0 = s + lane;
    unsigned er = (j0 < end) ? __ldcs(g_epack + j0) : 0u;
    for (int base = s; base < end; base += 32) {
        int m = min(32, end - base);
        unsigned cur_er = er;
        if (base + 32 < end) {
            int jn = base + 32 + lane;
            er = (jn < end) ? __ldcs(g_epack + jn) : 0u;
        }
        int pairs = (m + 1) >> 1;
        for (int p = 0; p < pairs; p++) {
            int eidx = (p << 1) + half;
            unsigned wd = __shfl_sync(0xffffffffu, cur_er, eidx);
            if (eidx < m) {
                int idx = (int)(wd & 0x3ffffu);
                unsigned short hb = (unsigned short)((wd >> 18) << 1);
                float vv = __half2float(__ushort_as_half(hb));
                acc_step_h(idx, vv, sub, acc);
            }
        }
    }

    #pragma unroll
    for (int i = 0; i < 8; i++) acc[i] += __shfl_xor_sync(0xffffffffu, acc[i], 16);

    // each half-warp writes its 16B slice; streaming store (out is write-once)
    int colbase = sub * 8 + half * 4;
    float4 xv = __ldcs(reinterpret_cast<const float4*>(x + (size_t)w * D + colbase));
    float a0 = acc[half * 4 + 0], a1 = acc[half * 4 + 1];
    float a2 = acc[half * 4 + 2], a3 = acc[half * 4 + 3];
    __stcs(reinterpret_cast<float4*>(out + (size_t)w * D + colbase),
           make_float4(xv.x - 2.f * a0, xv.y - 2.f * a1,
                       xv.z - 2.f * a2, xv.w - 2.f * a3));
}

// ---------------- launch -----------------------------------------------------

extern "C" void kernel_launch(void* const* d_in, const int* in_sizes, int n_in,
                              void* d_out, int out_size) {
    const float* vals = (const float*)d_in[0];
    const float* x    = (const float*)d_in[1];
    const int*   rows = (const int*)d_in[2];
    const int*   cols = (const int*)d_in[3];
    float*       out  = (float*)d_out;

    const int nnz = in_sizes[0];

    float2* dc_ptr;  cudaGetSymbolAddress((void**)&dc_ptr,  g_degcnt);
    int*    off_ptr; cudaGetSymbolAddress((void**)&off_ptr, g_off);
    int*    cur_ptr; cudaGetSymbolAddress((void**)&cur_ptr, g_cur);
    int*    bs_ptr;  cudaGetSymbolAddress((void**)&bs_ptr,  g_bsums);

    const int T = 256;

    // 1. zero (deg,count) pairs
    zero_i4_kernel<<<(N_BOTH * 2 / 4 + T - 1) / T, T>>>((int4*)dc_ptr, N_BOTH * 2 / 4);

    // 2. fused: degree/count histogram + per-row int8 quantization of x
    {
        int ablocks = (nnz + T - 1) / T;
        long long qthreads = (long long)N_ITEMS * 32;
        int qblocks = (int)((qthreads + T - 1) / T);
        front_kernel<<<ablocks + qblocks, T>>>(vals, rows, cols,
                                               (const float4*)x, nnz, ablocks);
    }

    // 3. unified exclusive scan over all 300k counts (prep fused into phase 1)
    {
        int nb = (N_BOTH + SCAN_B - 1) / SCAN_B;
        scan_block_kernel<<<nb, SCAN_B>>>(off_ptr, bs_ptr, N_BOTH);
        scan_sums_kernel<<<1, SCAN_B>>>(bs_ptr, nb);
        scan_add_kernel<<<nb, SCAN_B>>>(off_ptr, cur_ptr, bs_ptr, N_BOTH);
    }

    // 4. scatter packed edges into unified [CSR | CSC] (CSR folds x scale)
    build_kernel<<<(nnz + T - 1) / T, T>>>(vals, rows, cols, nnz);

    // 5. SpMM pass 1: y = A_norm @ x   (int8 gather, no atomics)
    {
        long long threads = (long long)N_USERS * 32;
        spmm1_kernel<<<(unsigned)((threads + T - 1) / T), T>>>(N_USERS);
    }

    // 6. SpMM pass 2 + finalize: out = x - 2 * (A_norm^T @ y)
    {
        long long threads = (long long)N_ITEMS * 32;
        spmm2_kernel<<<(unsigned)((threads + T - 1) / T), T>>>(x, out, N_ITEMS);
    }
}

// round 13
// speedup vs baseline: 1.0689x; 1.0689x over previous
#include <cuda_runtime.h>
#include <cuda_fp16.h>
#include <stdint.h>

// Problem constants (match reference_code)
#define N_USERS 200000
#define N_ITEMS 100000
#define N_BOTH  (N_USERS + N_ITEMS)
#define NNZ_CAP 5000000
#define D       128           // feature dim
#define SCAN_B  1024

// ---------------- scratch (device globals; no runtime allocation) ----------
__device__ __half   g_yh[(size_t)N_USERS * D];   // fp16 intermediate, 51.2 MB
__device__ __half   g_xh[(size_t)N_ITEMS * D];   // fp16 copy of x, 25.6 MB
__device__ float2   g_degcnt[N_BOTH];            // (deg, count) per node
__device__ float    g_dinv[N_BOTH];              // clamp(deg,1)^-0.5
__device__ int      g_off[N_BOTH];               // unified exclusive-scan offsets
__device__ int      g_cur[N_BOTH];               // working cursors for scatter
__device__ int      g_bsums[SCAN_B];             // scan block sums scratch
__device__ unsigned g_epack[(size_t)2 * NNZ_CAP]; // packed [CSR | CSC], 40 MB
// CSR word: (halfbits(nv) << 17) | col      (col < 2^17, nv sign always 0)
// CSC word: (((halfbits(nv)+1)>>1) << 18) | row  (row < 2^18, 14-bit nv)

// ---------------- helpers ----------------------------------------------------

__device__ __forceinline__ void red_add_v2(float2* addr, float a, float b) {
    asm volatile("red.global.add.v2.f32 [%0], {%1, %2};"
                 :: "l"(addr), "f"(a), "f"(b) : "memory");
}

// ---------------- kernels ---------------------------------------------------

__global__ void zero_i4_kernel(int4* __restrict__ p, int n4) {
    int i = blockIdx.x * blockDim.x + threadIdx.x;
    if (i < n4) p[i] = make_int4(0, 0, 0, 0);
}

// fused: [0, ablocks) = degree+count histogram (2 edges/thread for MLP);
// [ablocks, ...) = x -> fp16 cvt.
__global__ void front_kernel(const float* __restrict__ vals,
                             const int* __restrict__ rows,
                             const int* __restrict__ cols,
                             const float4* __restrict__ x,
                             int nnz, int ablocks, int n4) {
    if (blockIdx.x < (unsigned)ablocks) {
        int t = blockIdx.x * blockDim.x + threadIdx.x;
        int e = t * 2;
        if (e >= nnz) return;
        if (e + 1 < nnz) {
            float2 v = __ldcs(reinterpret_cast<const float2*>(vals + e));
            int2   r = __ldcs(reinterpret_cast<const int2*>(rows + e));
            int2   c = __ldcs(reinterpret_cast<const int2*>(cols + e));
            red_add_v2(&g_degcnt[r.x], v.x, 1.0f);
            red_add_v2(&g_degcnt[c.x + N_USERS], v.x, 1.0f);
            red_add_v2(&g_degcnt[r.y], v.y, 1.0f);
            red_add_v2(&g_degcnt[c.y + N_USERS], v.y, 1.0f);
        } else {
            float v = __ldcs(vals + e);
            red_add_v2(&g_degcnt[__ldcs(rows + e)], v, 1.0f);
            red_add_v2(&g_degcnt[__ldcs(cols + e) + N_USERS], v, 1.0f);
        }
    } else {
        int i = (blockIdx.x - ablocks) * blockDim.x + threadIdx.x;
        if (i >= n4) return;
        float4 v = __ldg(x + i);
        __half2 h0 = __floats2half2_rn(v.x, v.y);
        __half2 h1 = __floats2half2_rn(v.z, v.w);
        reinterpret_cast<uint2*>(g_xh)[i] =
            make_uint2(*(unsigned*)&h0, *(unsigned*)&h1);
    }
}

// ---- unified exclusive scan over all N_BOTH counts, with fused prep -------
__global__ void scan_block_kernel(int* __restrict__ out, int* __restrict__ bsums,
                                  int n) {
    __shared__ int sh[SCAN_B];
    int i = blockIdx.x * SCAN_B + threadIdx.x;
    int v = 0;
    if (i < n) {
        float2 dc = g_degcnt[i];
        v = (int)dc.y;
        g_dinv[i] = rsqrtf(fmaxf(dc.x, 1.0f));
    }
    sh[threadIdx.x] = v;
    __syncthreads();
    #pragma unroll
    for (int off = 1; off < SCAN_B; off <<= 1) {
        int t = (threadIdx.x >= (unsigned)off) ? sh[threadIdx.x - off] : 0;
        __syncthreads();
        sh[threadIdx.x] += t;
        __syncthreads();
    }
    if (i < n) out[i] = sh[threadIdx.x] - v;          // exclusive
    if (threadIdx.x == SCAN_B - 1) bsums[blockIdx.x] = sh[SCAN_B - 1];
}

__global__ void scan_sums_kernel(int* __restrict__ bsums, int nb) {
    __shared__ int sh[SCAN_B];
    int v = (threadIdx.x < (unsigned)nb) ? bsums[threadIdx.x] : 0;
    sh[threadIdx.x] = v;
    __syncthreads();
    #pragma unroll
    for (int off = 1; off < SCAN_B; off <<= 1) {
        int t = (threadIdx.x >= (unsigned)off) ? sh[threadIdx.x - off] : 0;
        __syncthreads();
        sh[threadIdx.x] += t;
        __syncthreads();
    }
    if (threadIdx.x < (unsigned)nb) bsums[threadIdx.x] = sh[threadIdx.x] - v;  // exclusive
}

__global__ void scan_add_kernel(int* __restrict__ off_, int* __restrict__ cur,
                                const int* __restrict__ bsums, int n) {
    int i = blockIdx.x * SCAN_B + threadIdx.x;
    if (i < n) {
        int o = off_[i] + bsums[blockIdx.x];
        off_[i] = o;
        cur[i] = o;
    }
}

// scatter packed edges into unified [CSR | CSC]; 2 edges/thread for MLP
__device__ __forceinline__ void build_one(int r, int c, float v) {
    float nv = v * g_dinv[r] * g_dinv[c + N_USERS];
    unsigned hb = (unsigned)__half_as_ushort(__float2half_rn(nv));  // sign bit 0
    unsigned wu = (hb << 17) | (unsigned)c;
    unsigned wi = (((hb + 1u) >> 1) << 18) | (unsigned)r;
    int pu = atomicAdd(&g_cur[r], 1);
    __stcs(g_epack + pu, wu);
    int pi = atomicAdd(&g_cur[c + N_USERS], 1);
    __stcs(g_epack + pi, wi);
}

__global__ void build_kernel(const float* __restrict__ vals,
                             const int* __restrict__ rows,
                             const int* __restrict__ cols,
                             int nnz) {
    int t = blockIdx.x * blockDim.x + threadIdx.x;
    int e = t * 2;
    if (e >= nnz) return;
    if (e + 1 < nnz) {
        float2 v = __ldcs(reinterpret_cast<const float2*>(vals + e));
        int2   r = __ldcs(reinterpret_cast<const int2*>(rows + e));
        int2   c = __ldcs(reinterpret_cast<const int2*>(cols + e));
        build_one(r.x, c.x, v.x);
        build_one(r.y, c.y, v.y);
    } else {
        build_one(__ldcs(rows + e), __ldcs(cols + e), __ldcs(vals + e));
    }
}

// shared inner step: gather 16 bytes (8 halves) and accumulate
__device__ __forceinline__ void acc_step(const __half* __restrict__ src,
                                         int idx, float vv, int sub,
                                         float* acc) {
    uint4 u = __ldg(reinterpret_cast<const uint4*>(src + (size_t)idx * D) + sub);
    __half2 h0 = *(__half2*)&u.x, h1 = *(__half2*)&u.y;
    __half2 h2 = *(__half2*)&u.z, h3 = *(__half2*)&u.w;
    float2 f0 = __half22float2(h0), f1 = __half22float2(h1);
    float2 f2 = __half22float2(h2), f3 = __half22float2(h3);
    acc[0] += vv * f0.x; acc[1] += vv * f0.y;
    acc[2] += vv * f1.x; acc[3] += vv * f1.y;
    acc[4] += vv * f2.x; acc[5] += vv * f2.y;
    acc[6] += vv * f3.x; acc[7] += vv * f3.y;
}

// row-accumulate loop over packed edge span [s, end): 2 edges/iter, 16 lanes
// each; software-pipelined record loads; one shuffle + decode per pair.
template<int IDX_BITS, int NV_LSH>
__device__ __forceinline__ void row_loop(const __half* __restrict__ src,
                                         int s, int end, int lane, int half,
                                         int sub, float* acc) {
    const unsigned IDX_MASK = (1u << IDX_BITS) - 1u;
    int j0 = s + lane;
    unsigned er = (j0 < end) ? __ldcs(g_epack + j0) : 0u;
    for (int base = s; base < end; base += 32) {
        int m = min(32, end - base);
        unsigned cur_er = er;
        if (base + 32 < end) {
            int jn = base + 32 + lane;
            er = (jn < end) ? __ldcs(g_epack + jn) : 0u;
        }
        int pairs = (m + 1) >> 1;
        for (int p = 0; p < pairs; p++) {
            int eidx = (p << 1) + half;
            unsigned w = __shfl_sync(0xffffffffu, cur_er, eidx);
            if (eidx < m) {
                int idx = (int)(w & IDX_MASK);
                unsigned short hb = (unsigned short)((w >> IDX_BITS) << NV_LSH);
                float vv = __half2float(__ushort_as_half(hb));
                acc_step(src, idx, vv, sub, acc);
            }
        }
    }
}

// pass 1: y[u, :] = sum_{e in row u} nv_e * x_h[col_e, :]
__global__ void spmm1_kernel(int nrows) {
    int w    = (blockIdx.x * blockDim.x + threadIdx.x) >> 5;
    int lane = threadIdx.x & 31;
    if (w >= nrows) return;
    int half = lane >> 4;
    int sub  = lane & 15;

    int s   = __ldg(&g_off[w]);
    int cnt = (int)__ldg(&g_degcnt[w].y);
    int end = s + cnt;

    float acc[8];
    #pragma unroll
    for (int i = 0; i < 8; i++) acc[i] = 0.f;

    row_loop<17, 0>(g_xh, s, end, lane, half, sub, acc);

    #pragma unroll
    for (int i = 0; i < 8; i++) acc[i] += __shfl_xor_sync(0xffffffffu, acc[i], 16);

    if (half == 0) {
        __half2 o0 = __floats2half2_rn(acc[0], acc[1]);
        __half2 o1 = __floats2half2_rn(acc[2], acc[3]);
        __half2 o2 = __floats2half2_rn(acc[4], acc[5]);
        __half2 o3 = __floats2half2_rn(acc[6], acc[7]);
        reinterpret_cast<uint4*>(g_yh + (size_t)w * D)[sub] =
            make_uint4(*(unsigned*)&o0, *(unsigned*)&o1,
                       *(unsigned*)&o2, *(unsigned*)&o3);
    }
}

// pass 2 + finalize: out[i, :] = x[i, :] - 2 * sum_{e in col i} nv_e * y_h[row_e, :]
__global__ void spmm2_kernel(const float* __restrict__ x,
                             float* __restrict__ out, int nrows) {
    int w    = (blockIdx.x * blockDim.x + threadIdx.x) >> 5;
    int lane = threadIdx.x & 31;
    if (w >= nrows) return;
    int half = lane >> 4;
    int sub  = lane & 15;

    int s   = __ldg(&g_off[w + N_USERS]);
    int cnt = (int)__ldg(&g_degcnt[w + N_USERS].y);
    int end = s + cnt;

    float acc[8];
    #pragma unroll
    for (int i = 0; i < 8; i++) acc[i] = 0.f;

    row_loop<18, 1>(g_yh, s, end, lane, half, sub, acc);

    #pragma unroll
    for (int i = 0; i < 8; i++) acc[i] += __shfl_xor_sync(0xffffffffu, acc[i], 16);

    // each half-warp writes its 16B slice; streaming store (out is write-once)
    int colbase = sub * 8 + half * 4;
    float4 xv = __ldcs(reinterpret_cast<const float4*>(x + (size_t)w * D + colbase));
    float a0 = acc[half * 4 + 0], a1 = acc[half * 4 + 1];
    float a2 = acc[half * 4 + 2], a3 = acc[half * 4 + 3];
    __stcs(reinterpret_cast<float4*>(out + (size_t)w * D + colbase),
           make_float4(xv.x - 2.f * a0, xv.y - 2.f * a1,
                       xv.z - 2.f * a2, xv.w - 2.f * a3));
}

// ---------------- launch -----------------------------------------------------

extern "C" void kernel_launch(void* const* d_in, const int* in_sizes, int n_in,
                              void* d_out, int out_size) {
    const float* vals = (const float*)d_in[0];
    const float* x    = (const float*)d_in[1];
    const int*   rows = (const int*)d_in[2];
    const int*   cols = (const int*)d_in[3];
    float*       out  = (float*)d_out;

    const int nnz = in_sizes[0];

    float2* dc_ptr;  cudaGetSymbolAddress((void**)&dc_ptr,  g_degcnt);
    int*    off_ptr; cudaGetSymbolAddress((void**)&off_ptr, g_off);
    int*    cur_ptr; cudaGetSymbolAddress((void**)&cur_ptr, g_cur);
    int*    bs_ptr;  cudaGetSymbolAddress((void**)&bs_ptr,  g_bsums);

    const int T = 256;

    // 1. zero (deg,count) pairs
    zero_i4_kernel<<<(N_BOTH * 2 / 4 + T - 1) / T, T>>>((int4*)dc_ptr, N_BOTH * 2 / 4);

    // 2. fused: degree/count histogram (2 edges/thread) + x -> fp16 conversion
    {
        int npairs  = (nnz + 1) / 2;
        int ablocks = (npairs + T - 1) / T;
        int n4 = N_ITEMS * D / 4;
        int bblocks = (n4 + T - 1) / T;
        front_kernel<<<ablocks + bblocks, T>>>(vals, rows, cols,
                                               (const float4*)x, nnz, ablocks, n4);
    }

    // 3. unified exclusive scan over all 300k counts (prep fused into phase 1)
    {
        int nb = (N_BOTH + SCAN_B - 1) / SCAN_B;
        scan_block_kernel<<<nb, SCAN_B>>>(off_ptr, bs_ptr, N_BOTH);
        scan_sums_kernel<<<1, SCAN_B>>>(bs_ptr, nb);
        scan_add_kernel<<<nb, SCAN_B>>>(off_ptr, cur_ptr, bs_ptr, N_BOTH);
    }

    // 4. scatter packed edges into unified [CSR | CSC], 2 edges/thread
    {
        int npairs = (nnz + 1) / 2;
        build_kernel<<<(npairs + T - 1) / T, T>>>(vals, rows, cols, nnz);
    }

    // 5. SpMM pass 1: y = A_norm @ x   (fp16 gather, no atomics)
    {
        long long threads = (long long)N_USERS * 32;
        spmm1_kernel<<<(unsigned)((threads + T - 1) / T), T>>>(N_USERS);
    }

    // 6. SpMM pass 2 + finalize: out = x - 2 * (A_norm^T @ y)
    {
        long long threads = (long long)N_ITEMS * 32;
        spmm2_kernel<<<(unsigned)((threads + T - 1) / T), T>>>(x, out, N_ITEMS);
    }
}